// round 2
// baseline (speedup 1.0000x reference)
#include <cuda_runtime.h>
#include <math.h>

// ---------------------------------------------------------------------------
// Shapes (fixed by the problem): N=90000, D=H=128, 2H=256, E=1.44M, G=3000,
// P = G*F*F = 675000. Scratch as __device__ globals (allocation-free rule).
// ---------------------------------------------------------------------------
#define MAXN 90112
#define MAXG 4096

__device__ float g_agg [MAXN * 128];   // 46 MB
__device__ float g_ht  [MAXN * 256];   // 92 MB  (GEMM1 output, pre-BN)
__device__ float g_h1  [MAXN * 128];
__device__ float g_h2  [MAXN * 128];
__device__ float g_mean[MAXN * 128];
__device__ float g_ls  [MAXN * 128];
__device__ float g_u   [MAXN];
__device__ float g_v   [MAXN];
__device__ float g_colsum[256];
__device__ float g_colsq [256];
__device__ float g_scale [256];
__device__ float g_shift [256];
__device__ float g_pool[MAXG];
__device__ float g_cnt [MAXG];
__device__ float g_acc [2];            // [0]=kl sum, [1]=numloss sum

// ---------------------------------------------------------------------------
// Edge scatter: agg[dst] += x[src].  One warp per edge, 128 floats = float4
// per lane, vector reduction (red.global.add.v4.f32).
// ---------------------------------------------------------------------------
__global__ void scatter_k(const float* __restrict__ X,
                          const int* __restrict__ ei, int E) {
    int gw   = (blockIdx.x * blockDim.x + threadIdx.x) >> 5;
    int lane = threadIdx.x & 31;
    if (gw >= E) return;
    int s = __ldg(ei + gw);
    int d = __ldg(ei + E + gw);
    float4 vv = *(const float4*)(X + (size_t)s * 128 + lane * 4);
    float* dst = g_agg + (size_t)d * 128 + lane * 4;
    asm volatile("red.global.add.v4.f32 [%0], {%1,%2,%3,%4};"
                 :: "l"(dst), "f"(vv.x), "f"(vv.y), "f"(vv.z), "f"(vv.w)
                 : "memory");
}

// ---------------------------------------------------------------------------
// GEMM1: OUT[N,256] = (X + AGG)[N,128] @ W[128,256] + bias
// Block: 64 rows x 64 cols, 256 threads, 4x4 microtile, BK=64.
// ---------------------------------------------------------------------------
__global__ void gemm_aggr_k(const float* __restrict__ X,
                            const float* __restrict__ W,
                            const float* __restrict__ bias,
                            float* __restrict__ OUT, int N) {
    __shared__ float As[64][64];   // [m][k]
    __shared__ float Ws[64][64];   // [k][n]
    int tid = threadIdx.x;
    int tx = tid & 15, ty = tid >> 4;
    int lr = tid >> 4;              // 0..15 (load row group)
    int lc = (tid & 15) * 4;        // 0..60 (load col *4)
    int row0 = blockIdx.y * 64;
    int n0   = blockIdx.x * 64;
    float acc[4][4] = {};

    for (int kk = 0; kk < 128; kk += 64) {
        #pragma unroll
        for (int q = 0; q < 4; q++) {
            int m  = lr + q * 16;
            int rg = row0 + m;
            float4 a = make_float4(0.f, 0.f, 0.f, 0.f);
            if (rg < N) {
                size_t off = (size_t)rg * 128 + kk + lc;
                float4 xv = *(const float4*)(X + off);
                float4 av = *(const float4*)(g_agg + off);
                a.x = xv.x + av.x; a.y = xv.y + av.y;
                a.z = xv.z + av.z; a.w = xv.w + av.w;
            }
            *(float4*)&As[m][lc] = a;
            int k = lr + q * 16;
            *(float4*)&Ws[k][lc] = *(const float4*)(W + (size_t)(kk + k) * 256 + n0 + lc);
        }
        __syncthreads();
        #pragma unroll 8
        for (int k = 0; k < 64; k++) {
            float4 w = *(float4*)&Ws[k][tx * 4];
            float a0 = As[ty * 4 + 0][k];
            float a1 = As[ty * 4 + 1][k];
            float a2 = As[ty * 4 + 2][k];
            float a3 = As[ty * 4 + 3][k];
            acc[0][0] += a0 * w.x; acc[0][1] += a0 * w.y; acc[0][2] += a0 * w.z; acc[0][3] += a0 * w.w;
            acc[1][0] += a1 * w.x; acc[1][1] += a1 * w.y; acc[1][2] += a1 * w.z; acc[1][3] += a1 * w.w;
            acc[2][0] += a2 * w.x; acc[2][1] += a2 * w.y; acc[2][2] += a2 * w.z; acc[2][3] += a2 * w.w;
            acc[3][0] += a3 * w.x; acc[3][1] += a3 * w.y; acc[3][2] += a3 * w.z; acc[3][3] += a3 * w.w;
        }
        __syncthreads();
    }
    float4 bv = *(const float4*)(bias + n0 + tx * 4);
    #pragma unroll
    for (int i = 0; i < 4; i++) {
        int rg = row0 + ty * 4 + i;
        if (rg < N) {
            float4 o;
            o.x = acc[i][0] + bv.x; o.y = acc[i][1] + bv.y;
            o.z = acc[i][2] + bv.z; o.w = acc[i][3] + bv.w;
            *(float4*)(OUT + (size_t)rg * 256 + n0 + tx * 4) = o;
        }
    }
}

// ---------------------------------------------------------------------------
// Column stats of ht [N,256] -> g_colsum/g_colsq (atomics per 256-row block).
// ---------------------------------------------------------------------------
__global__ void stats_k(const float* __restrict__ HT, int N) {
    int c  = threadIdx.x;               // 256 threads = 256 cols
    int r0 = blockIdx.x * 256;
    int rend = min(r0 + 256, N);
    float s = 0.f, sq = 0.f;
    for (int r = r0; r < rend; r++) {
        float v = HT[(size_t)r * 256 + c];
        s += v; sq += v * v;
    }
    atomicAdd(&g_colsum[c], s);
    atomicAdd(&g_colsq[c], sq);
}

__global__ void bnfin_k(const float* __restrict__ gamma,
                        const float* __restrict__ beta, int N) {
    int c = threadIdx.x;
    float invN = 1.0f / (float)N;
    float mu  = g_colsum[c] * invN;
    float var = g_colsq[c] * invN - mu * mu;
    float sc  = gamma[c] * rsqrtf(var + 1e-5f);
    g_scale[c] = sc;
    g_shift[c] = beta[c] - mu * sc;
}

// ---------------------------------------------------------------------------
// GEMM2: OUT[N,128] = BN(ht)[N,256] @ W2[256,128] + b2   (optional ReLU)
// ---------------------------------------------------------------------------
__global__ void gemm_bn_k(const float* __restrict__ HT,
                          const float* __restrict__ W,
                          const float* __restrict__ bias,
                          float* __restrict__ OUT, int relu, int N) {
    __shared__ float As[64][64];
    __shared__ float Ws[64][64];
    int tid = threadIdx.x;
    int tx = tid & 15, ty = tid >> 4;
    int lr = tid >> 4;
    int lc = (tid & 15) * 4;
    int row0 = blockIdx.y * 64;
    int n0   = blockIdx.x * 64;
    float acc[4][4] = {};

    for (int kk = 0; kk < 256; kk += 64) {
        float4 sc4 = *(const float4*)(g_scale + kk + lc);
        float4 sh4 = *(const float4*)(g_shift + kk + lc);
        #pragma unroll
        for (int q = 0; q < 4; q++) {
            int m  = lr + q * 16;
            int rg = row0 + m;
            float4 a = make_float4(0.f, 0.f, 0.f, 0.f);
            if (rg < N) {
                float4 h4 = *(const float4*)(HT + (size_t)rg * 256 + kk + lc);
                a.x = h4.x * sc4.x + sh4.x;
                a.y = h4.y * sc4.y + sh4.y;
                a.z = h4.z * sc4.z + sh4.z;
                a.w = h4.w * sc4.w + sh4.w;
                if (relu) {
                    a.x = fmaxf(a.x, 0.f); a.y = fmaxf(a.y, 0.f);
                    a.z = fmaxf(a.z, 0.f); a.w = fmaxf(a.w, 0.f);
                }
            }
            *(float4*)&As[m][lc] = a;
            int k = lr + q * 16;
            *(float4*)&Ws[k][lc] = *(const float4*)(W + (size_t)(kk + k) * 128 + n0 + lc);
        }
        __syncthreads();
        #pragma unroll 8
        for (int k = 0; k < 64; k++) {
            float4 w = *(float4*)&Ws[k][tx * 4];
            float a0 = As[ty * 4 + 0][k];
            float a1 = As[ty * 4 + 1][k];
            float a2 = As[ty * 4 + 2][k];
            float a3 = As[ty * 4 + 3][k];
            acc[0][0] += a0 * w.x; acc[0][1] += a0 * w.y; acc[0][2] += a0 * w.z; acc[0][3] += a0 * w.w;
            acc[1][0] += a1 * w.x; acc[1][1] += a1 * w.y; acc[1][2] += a1 * w.z; acc[1][3] += a1 * w.w;
            acc[2][0] += a2 * w.x; acc[2][1] += a2 * w.y; acc[2][2] += a2 * w.z; acc[2][3] += a2 * w.w;
            acc[3][0] += a3 * w.x; acc[3][1] += a3 * w.y; acc[3][2] += a3 * w.z; acc[3][3] += a3 * w.w;
        }
        __syncthreads();
    }
    float4 bv = *(const float4*)(bias + n0 + tx * 4);
    #pragma unroll
    for (int i = 0; i < 4; i++) {
        int rg = row0 + ty * 4 + i;
        if (rg < N) {
            float4 o;
            o.x = acc[i][0] + bv.x; o.y = acc[i][1] + bv.y;
            o.z = acc[i][2] + bv.z; o.w = acc[i][3] + bv.w;
            *(float4*)(OUT + (size_t)rg * 128 + n0 + tx * 4) = o;
        }
    }
}

// ---------------------------------------------------------------------------
// z = noise*exp(logstd)+mean, fused: u=z.Wc[:128], v=z.Wc[128:], s=z.Wn,
// per-graph pooled sums via atomics, KL partial sums. One warp per node row.
// ---------------------------------------------------------------------------
__global__ void z_k(const float* __restrict__ MEAN, const float* __restrict__ LS,
                    const float* __restrict__ NOISE, const int* __restrict__ batch,
                    const float* __restrict__ Wn, const float* __restrict__ Wc,
                    int N) {
    __shared__ float klred[8];
    int lane = threadIdx.x & 31;
    int w    = threadIdx.x >> 5;
    int row  = blockIdx.x * 8 + w;
    float klp = 0.f;
    if (row < N) {
        size_t off = (size_t)row * 128 + lane * 4;
        float4 m4 = *(const float4*)(MEAN + off);
        float4 l4 = *(const float4*)(LS + off);
        float4 n4 = *(const float4*)(NOISE + off);
        float4 e4 = make_float4(expf(l4.x), expf(l4.y), expf(l4.z), expf(l4.w));
        float4 z4 = make_float4(n4.x * e4.x + m4.x, n4.y * e4.y + m4.y,
                                n4.z * e4.z + m4.z, n4.w * e4.w + m4.w);
        float4 wa = *(const float4*)(Wc + lane * 4);
        float4 wb = *(const float4*)(Wc + 128 + lane * 4);
        float4 wn = *(const float4*)(Wn + lane * 4);
        float up = z4.x * wa.x + z4.y * wa.y + z4.z * wa.z + z4.w * wa.w;
        float vp = z4.x * wb.x + z4.y * wb.y + z4.z * wb.z + z4.w * wb.w;
        float sp = z4.x * wn.x + z4.y * wn.y + z4.z * wn.z + z4.w * wn.w;
        klp = (1.f + 2.f * l4.x - m4.x * m4.x - e4.x * e4.x)
            + (1.f + 2.f * l4.y - m4.y * m4.y - e4.y * e4.y)
            + (1.f + 2.f * l4.z - m4.z * m4.z - e4.z * e4.z)
            + (1.f + 2.f * l4.w - m4.w * m4.w - e4.w * e4.w);
        #pragma unroll
        for (int o = 16; o > 0; o >>= 1) {
            up  += __shfl_xor_sync(0xffffffffu, up,  o);
            vp  += __shfl_xor_sync(0xffffffffu, vp,  o);
            sp  += __shfl_xor_sync(0xffffffffu, sp,  o);
            klp += __shfl_xor_sync(0xffffffffu, klp, o);
        }
        if (lane == 0) {
            g_u[row] = up;
            g_v[row] = vp;
            int b = batch[row];
            atomicAdd(&g_pool[b], sp);
            atomicAdd(&g_cnt[b], 1.0f);
        }
    }
    if (lane == 0) klred[w] = (row < N) ? klp : 0.f;
    __syncthreads();
    if (threadIdx.x == 0) {
        float t = 0.f;
        #pragma unroll
        for (int i = 0; i < 8; i++) t += klred[i];
        atomicAdd(&g_acc[0], t);
    }
}

// num_pred[g] = pool_s/count + bn; accumulate |num_pred - bridge_num|.
__global__ void num_k(const float* __restrict__ bridge_num,
                      const float* __restrict__ bnp,
                      float* __restrict__ out_np, int G) {
    __shared__ float red[256];
    int g = blockIdx.x * 256 + threadIdx.x;
    float d = 0.f;
    if (g < G) {
        float np = g_pool[g] / g_cnt[g] + bnp[0];
        out_np[g] = np;
        d = fabsf(np - bridge_num[g]);
    }
    red[threadIdx.x] = d;
    __syncthreads();
    for (int s = 128; s > 0; s >>= 1) {
        if (threadIdx.x < s) red[threadIdx.x] += red[threadIdx.x + s];
        __syncthreads();
    }
    if (threadIdx.x == 0) atomicAdd(&g_acc[1], red[0]);
}

// A_pred[p] = sigmoid(u[row0[p]] + v[row1[p]] + bc)
__global__ void apred_k(const int* __restrict__ bidx,
                        const float* __restrict__ bcp,
                        float* __restrict__ out, int P) {
    int p = blockIdx.x * 256 + threadIdx.x;
    if (p >= P) return;
    int i = __ldg(bidx + p);
    int j = __ldg(bidx + P + p);
    float logit = g_u[i] + g_v[j] + bcp[0];
    out[p] = 1.0f / (1.0f + expf(-logit));
}

__global__ void fin_k(float* __restrict__ out, int P, int N, int G) {
    out[P]     = 0.5f * g_acc[0] / ((float)N * (float)N);
    out[P + 1] = g_acc[1] / (float)G;
}

// ---------------------------------------------------------------------------
// Launcher
// ---------------------------------------------------------------------------
extern "C" void kernel_launch(void* const* d_in, const int* in_sizes, int n_in,
                              void* d_out, int out_size) {
    const float* x          = (const float*)d_in[0];
    const int*   ei         = (const int*)  d_in[1];
    const int*   batch      = (const int*)  d_in[2];
    const float* bridge_num = (const float*)d_in[3];
    const int*   bidx       = (const int*)  d_in[4];
    const float* noise      = (const float*)d_in[5];
    const float* W1s        = (const float*)d_in[6];
    const float* b1s        = (const float*)d_in[7];
    const float* gammas     = (const float*)d_in[8];
    const float* betas      = (const float*)d_in[9];
    const float* W2s        = (const float*)d_in[10];
    const float* b2s        = (const float*)d_in[11];
    const float* Wn         = (const float*)d_in[12];
    const float* bnp        = (const float*)d_in[13];
    const float* Wc         = (const float*)d_in[14];
    const float* bcp        = (const float*)d_in[15];
    float* out = (float*)d_out;

    int N = in_sizes[0] / 128;
    int E = in_sizes[1] / 2;
    int G = in_sizes[3];
    int P = in_sizes[4] / 2;

    float *agg, *ht, *h1, *h2, *mean, *ls, *colsum, *colsq, *pool, *cnt, *acc;
    cudaGetSymbolAddress((void**)&agg,    g_agg);
    cudaGetSymbolAddress((void**)&ht,     g_ht);
    cudaGetSymbolAddress((void**)&h1,     g_h1);
    cudaGetSymbolAddress((void**)&h2,     g_h2);
    cudaGetSymbolAddress((void**)&mean,   g_mean);
    cudaGetSymbolAddress((void**)&ls,     g_ls);
    cudaGetSymbolAddress((void**)&colsum, g_colsum);
    cudaGetSymbolAddress((void**)&colsq,  g_colsq);
    cudaGetSymbolAddress((void**)&pool,   g_pool);
    cudaGetSymbolAddress((void**)&cnt,    g_cnt);
    cudaGetSymbolAddress((void**)&acc,    g_acc);

    dim3 gemm1_grid(4, (N + 63) / 64);   // 256 cols
    dim3 gemm2_grid(2, (N + 63) / 64);   // 128 cols
    int scat_blocks = (E * 32 + 511) / 512;
    int stat_blocks = (N + 255) / 256;

    // One GIN layer: (optional scatter) -> GEMM1 -> stats -> BN -> GEMM2
    auto layer = [&](const float* in, int li, int relu, float* outbuf, bool do_scatter) {
        if (do_scatter) {
            cudaMemsetAsync(agg, 0, (size_t)N * 128 * sizeof(float));
            scatter_k<<<scat_blocks, 512>>>(in, ei, E);
        }
        cudaMemsetAsync(colsum, 0, 256 * sizeof(float));
        cudaMemsetAsync(colsq,  0, 256 * sizeof(float));
        gemm_aggr_k<<<gemm1_grid, 256>>>(in, W1s + (size_t)li * 128 * 256,
                                         b1s + li * 256, ht, N);
        stats_k<<<stat_blocks, 256>>>(ht, N);
        bnfin_k<<<1, 256>>>(gammas + li * 256, betas + li * 256, N);
        gemm_bn_k<<<gemm2_grid, 256>>>(ht, W2s + (size_t)li * 256 * 128,
                                       b2s + li * 128, outbuf, relu, N);
    };

    layer(x,  0, 1, h1,   true);
    layer(h1, 1, 1, h2,   true);
    layer(h2, 2, 0, mean, true);
    layer(h2, 3, 0, ls,   false);   // reuse agg(h2) from layer 2

    cudaMemsetAsync(pool, 0, G * sizeof(float));
    cudaMemsetAsync(cnt,  0, G * sizeof(float));
    cudaMemsetAsync(acc,  0, 2 * sizeof(float));
    z_k<<<(N + 7) / 8, 256>>>(mean, ls, noise, batch, Wn, Wc, N);
    num_k<<<(G + 255) / 256, 256>>>(bridge_num, bnp, out + P + 2, G);
    apred_k<<<(P + 255) / 256, 256>>>(bidx, bcp, out, P);
    fin_k<<<1, 1>>>(out, P, N, G);
}